// round 2
// baseline (speedup 1.0000x reference)
#include <cuda_runtime.h>

#define B_  32
#define S_  64
#define T_  32
#define H_  512
#define V_  32000
#define K3  1536

typedef unsigned long long ull;

// ---------------- device scratch ----------------
__device__ float g_Ukeys[B_ * S_ * H_];
__device__ float g_query[2][1024 * B_];   // [(l*512+h)][b], double buffered
__device__ float g_ginT[1024 * B_];       // rows 0..511 emb(x), 512..1023 context
__device__ float g_qp[4][H_ * B_];
__device__ float g_gh0p[2][K3 * B_];
__device__ float g_gh1p[2][K3 * B_];
__device__ float g_gi0p[4][K3 * B_];
__device__ float g_gi1p[2][K3 * B_];
__device__ float g_logits[B_ * V_];
__device__ int   g_tok[B_];

// ---------------- packed f32x2 helpers ----------------
__device__ __forceinline__ ull pk2(float a, float b) {
    ull r; asm("mov.b64 %0, {%1,%2};" : "=l"(r) : "f"(a), "f"(b)); return r;
}
__device__ __forceinline__ ull fma2(ull a, ull b, ull c) {
    ull d; asm("fma.rn.f32x2 %0, %1, %2, %3;" : "=l"(d) : "l"(a), "l"(b), "l"(c)); return d;
}
__device__ __forceinline__ void upk(ull v, float& lo, float& hi) {
    asm("mov.b64 {%0,%1}, %2;" : "=f"(lo), "=f"(hi) : "l"(v));
}

// ---------------- generic partial GEMM tile ----------------
// C[m0..m0+127][0..31] = W[m, k0..k0+255] @ X[k chunk][b], 128 threads.
__device__ __forceinline__ void gemm_tile(
    const float* __restrict__ W, int ldW,
    const float* __restrict__ Xchunk,   // 256*32 floats
    float* __restrict__ Cchunk,
    int m0, int k0, float* Xs)
{
    int tid = threadIdx.x;
    {
        const float4* src = (const float4*)Xchunk;
        float4* dst = (float4*)Xs;
        #pragma unroll
        for (int i = 0; i < 16; i++) dst[tid + 128 * i] = src[tid + 128 * i];
    }
    __syncthreads();

    int bt = tid & 3, mt = tid >> 2;
    int b0 = bt * 8;
    const float* wr0 = W + (size_t)(m0 + mt) * ldW + k0;

    ull acc[4][4];
    #pragma unroll
    for (int i = 0; i < 4; i++)
        #pragma unroll
        for (int j = 0; j < 4; j++) acc[i][j] = 0ULL;

    for (int kk = 0; kk < 256; kk += 4) {
        float4 w[4];
        #pragma unroll
        for (int i = 0; i < 4; i++)
            w[i] = *(const float4*)(wr0 + (size_t)i * 32 * ldW + kk);
        #pragma unroll
        for (int c = 0; c < 4; c++) {
            ull xp[4];
            #pragma unroll
            for (int j = 0; j < 4; j++)
                xp[j] = *(const ull*)&Xs[(kk + c) * 32 + b0 + 2 * j];
            #pragma unroll
            for (int i = 0; i < 4; i++) {
                const float* wf = reinterpret_cast<const float*>(&w[i]);
                ull wd = pk2(wf[c], wf[c]);
                #pragma unroll
                for (int j = 0; j < 4; j++) acc[i][j] = fma2(wd, xp[j], acc[i][j]);
            }
        }
    }
    __syncthreads();
    #pragma unroll
    for (int i = 0; i < 4; i++)
        #pragma unroll
        for (int j = 0; j < 4; j++)
            *(ull*)&Cchunk[(size_t)(m0 + mt + i * 32) * 32 + b0 + 2 * j] = acc[i][j];
}

// ---------------- init ----------------
__global__ void k_init(const float* __restrict__ ehid) {
    int idx = blockIdx.x * 256 + threadIdx.x;   // 32768
    int row = idx >> 5, b = idx & 31;
    int l = row >> 9, h = row & 511;
    g_query[0][row * 32 + b] = ehid[((size_t)l * 32 + b) * 512 + h];
    if (idx < B_) g_tok[idx] = 1;  // BOS
}

// ---------------- Ukeys = enc @ Ua^T + bua ----------------
__global__ __launch_bounds__(256) void k_ukeys(
    const float* __restrict__ enc, const float* __restrict__ Ua,
    const float* __restrict__ bua)
{
    __shared__ float es[8 * 512];
    int row0 = blockIdx.x * 8;   // grid 256
    int tid = threadIdx.x;
    {
        const float4* src = (const float4*)(enc + (size_t)row0 * 512);
        #pragma unroll
        for (int i = 0; i < 4; i++) ((float4*)es)[tid + 256 * i] = src[tid + 256 * i];
    }
    __syncthreads();
    int h = tid;
    float acc0[8], acc1[8];
    #pragma unroll
    for (int r = 0; r < 8; r++) { acc0[r] = 0.f; acc1[r] = 0.f; }
    const float* u0 = Ua + (size_t)h * 512;
    const float* u1 = Ua + (size_t)(h + 256) * 512;
    for (int k = 0; k < 512; k++) {
        float w0 = u0[k], w1 = u1[k];
        #pragma unroll
        for (int r = 0; r < 8; r++) {
            float x = es[r * 512 + k];
            acc0[r] += w0 * x; acc1[r] += w1 * x;
        }
    }
    float bb0 = bua[h], bb1 = bua[h + 256];
    #pragma unroll
    for (int r = 0; r < 8; r++) {
        g_Ukeys[(size_t)(row0 + r) * 512 + h]       = acc0[r] + bb0;
        g_Ukeys[(size_t)(row0 + r) * 512 + h + 256] = acc1[r] + bb1;
    }
}

// ---------------- pre-GEMMs: q, Gh0, Gh1 ----------------
__global__ __launch_bounds__(128) void k_pre3(
    const float* __restrict__ Wa, const float* __restrict__ Whh0,
    const float* __restrict__ Whh1, int par)
{
    __shared__ float Xs[8192];
    const float* qprev = (const float*)g_query[par];
    int blk = blockIdx.x;
    if (blk < 16) {                 // q: M=512, K=1024
        int mt = blk >> 2, ks = blk & 3;
        gemm_tile(Wa, 1024, qprev + ks * 8192, g_qp[ks], mt * 128, ks * 256, Xs);
    } else if (blk < 40) {          // Gh0: M=1536, K=512 (X = h0_prev)
        int tt = blk - 16; int mt = tt >> 1, ks = tt & 1;
        gemm_tile(Whh0, 512, qprev + ks * 8192, g_gh0p[ks], mt * 128, ks * 256, Xs);
    } else {                        // Gh1: X = h1_prev
        int tt = blk - 40; int mt = tt >> 1, ks = tt & 1;
        gemm_tile(Whh1, 512, qprev + 512 * 32 + ks * 8192, g_gh1p[ks], mt * 128, ks * 256, Xs);
    }
}

// ---------------- Gi GEMM ----------------
__global__ __launch_bounds__(128) void k_gi(
    const float* __restrict__ W, int ldW, int nks, int xsel, int xpar, int csel)
{
    __shared__ float Xs[8192];
    int mt = blockIdx.x / nks, ks = blockIdx.x % nks;
    const float* X = xsel ? (const float*)g_query[xpar] : (const float*)g_ginT;
    float* Cp = csel ? g_gi1p[ks] : g_gi0p[ks];
    gemm_tile(W, ldW, X + ks * 8192, Cp, mt * 128, ks * 256, Xs);
}

// ---------------- attention + build ginT ----------------
__global__ __launch_bounds__(256) void k_attn(
    const float* __restrict__ enc, const float* __restrict__ emb,
    const float* __restrict__ Va, const float* __restrict__ bva,
    const float* __restrict__ ba, float* __restrict__ attn_out, int t)
{
    int b = blockIdx.x, tid = threadIdx.x;
    __shared__ float qs[512], vas[512], sc[64], ws[64];
    for (int h = tid; h < 512; h += 256) {
        qs[h] = g_qp[0][h * 32 + b] + g_qp[1][h * 32 + b]
              + g_qp[2][h * 32 + b] + g_qp[3][h * 32 + b] + ba[h];
        vas[h] = Va[h];
    }
    __syncthreads();
    int wid = tid >> 5, lane = tid & 31;
    for (int s = wid; s < 64; s += 8) {
        const float* uk = g_Ukeys + ((size_t)(b * 64 + s)) * 512;
        float acc = 0.f;
        for (int h = lane; h < 512; h += 32)
            acc += vas[h] * tanhf(qs[h] + uk[h]);
        #pragma unroll
        for (int o = 16; o; o >>= 1) acc += __shfl_xor_sync(0xffffffffu, acc, o);
        if (lane == 0) sc[s] = acc + bva[0];
    }
    __syncthreads();
    if (tid == 0) {
        float m = sc[0];
        for (int s = 1; s < 64; s++) m = fmaxf(m, sc[s]);
        float sum = 0.f;
        for (int s = 0; s < 64; s++) { float e = expf(sc[s] - m); ws[s] = e; sum += e; }
        float inv = 1.f / sum;
        for (int s = 0; s < 64; s++) ws[s] *= inv;
    }
    __syncthreads();
    if (tid < 64 && attn_out)
        attn_out[((size_t)b * T_ + t) * 64 + tid] = ws[tid];
    int tok = g_tok[b];
    for (int h = tid; h < 512; h += 256) {
        float c = 0.f;
        const float* e = enc + ((size_t)b * 64) * 512 + h;
        #pragma unroll 8
        for (int s = 0; s < 64; s++) c += ws[s] * e[(size_t)s * 512];
        g_ginT[(512 + h) * 32 + b] = c;
        g_ginT[h * 32 + b] = emb[(size_t)tok * 512 + h];
    }
}

// ---------------- GRU gate combine ----------------
__global__ __launch_bounds__(256) void k_comb(
    int layer, int par, const float* __restrict__ bih, const float* __restrict__ bhh)
{
    int idx = blockIdx.x * 256 + threadIdx.x;   // 16384
    int j = idx >> 5, b = idx & 31;
    int o_r = j * 32 + b, o_z = (j + 512) * 32 + b, o_n = (j + 1024) * 32 + b;
    float gir, giz, gin_, ghr, ghz, ghn, hp;
    if (layer == 0) {
        gir  = g_gi0p[0][o_r] + g_gi0p[1][o_r] + g_gi0p[2][o_r] + g_gi0p[3][o_r];
        giz  = g_gi0p[0][o_z] + g_gi0p[1][o_z] + g_gi0p[2][o_z] + g_gi0p[3][o_z];
        gin_ = g_gi0p[0][o_n] + g_gi0p[1][o_n] + g_gi0p[2][o_n] + g_gi0p[3][o_n];
        ghr = g_gh0p[0][o_r] + g_gh0p[1][o_r];
        ghz = g_gh0p[0][o_z] + g_gh0p[1][o_z];
        ghn = g_gh0p[0][o_n] + g_gh0p[1][o_n];
        hp = g_query[par][j * 32 + b];
    } else {
        gir  = g_gi1p[0][o_r] + g_gi1p[1][o_r];
        giz  = g_gi1p[0][o_z] + g_gi1p[1][o_z];
        gin_ = g_gi1p[0][o_n] + g_gi1p[1][o_n];
        ghr = g_gh1p[0][o_r] + g_gh1p[1][o_r];
        ghz = g_gh1p[0][o_z] + g_gh1p[1][o_z];
        ghn = g_gh1p[0][o_n] + g_gh1p[1][o_n];
        hp = g_query[par][(512 + j) * 32 + b];
    }
    gir += bih[j];         ghr += bhh[j];
    giz += bih[j + 512];   ghz += bhh[j + 512];
    gin_ += bih[j + 1024]; ghn += bhh[j + 1024];
    float r = 1.f / (1.f + expf(-(gir + ghr)));
    float z = 1.f / (1.f + expf(-(giz + ghz)));
    float n = tanhf(gin_ + r * ghn);
    float h = (1.f - z) * n + z * hp;
    int off = layer ? 512 : 0;
    g_query[par ^ 1][(off + j) * 32 + b] = h;
}

// ---------------- logits ----------------
__global__ __launch_bounds__(128) void k_logits(
    const float* __restrict__ outW, const float* __restrict__ outb, int parN)
{
    __shared__ float Xs[8192];
    int tid = threadIdx.x;
    int bt = tid & 3, mt = tid >> 2;
    int b0 = bt * 8;
    int v0 = blockIdx.x * 128;   // grid 250
    ull acc[4][4];
    #pragma unroll
    for (int i = 0; i < 4; i++)
        #pragma unroll
        for (int j = 0; j < 4; j++) acc[i][j] = 0ULL;

    const float* h1T = (const float*)g_query[parN] + 512 * 32;
    for (int ck = 0; ck < 2; ck++) {
        if (ck) __syncthreads();
        {
            const float4* src = (const float4*)(h1T + ck * 8192);
            float4* dst = (float4*)Xs;
            #pragma unroll
            for (int i = 0; i < 16; i++) dst[tid + 128 * i] = src[tid + 128 * i];
        }
        __syncthreads();
        const float* wr = outW + (size_t)(v0 + mt) * 512 + ck * 256;
        for (int kk = 0; kk < 256; kk += 4) {
            float4 w[4];
            #pragma unroll
            for (int i = 0; i < 4; i++)
                w[i] = *(const float4*)(wr + (size_t)i * 32 * 512 + kk);
            #pragma unroll
            for (int c = 0; c < 4; c++) {
                ull xp[4];
                #pragma unroll
                for (int j = 0; j < 4; j++)
                    xp[j] = *(const ull*)&Xs[(kk + c) * 32 + b0 + 2 * j];
                #pragma unroll
                for (int i = 0; i < 4; i++) {
                    const float* wf = reinterpret_cast<const float*>(&w[i]);
                    ull wd = pk2(wf[c], wf[c]);
                    #pragma unroll
                    for (int j = 0; j < 4; j++) acc[i][j] = fma2(wd, xp[j], acc[i][j]);
                }
            }
        }
    }
    #pragma unroll
    for (int i = 0; i < 4; i++) {
        int v = v0 + mt + i * 32;
        float bb = outb[v];
        #pragma unroll
        for (int j = 0; j < 4; j++) {
            float lo, hi; upk(acc[i][j], lo, hi);
            g_logits[(size_t)(b0 + 2 * j) * V_ + v]     = lo + bb;
            g_logits[(size_t)(b0 + 2 * j + 1) * V_ + v] = hi + bb;
        }
    }
}

// ---------------- log_softmax + argmax ----------------
__global__ __launch_bounds__(256) void k_softmax(float* __restrict__ lp_out, int t)
{
    int b = blockIdx.x, tid = threadIdx.x;
    const float* lg = g_logits + (size_t)b * V_;
    __shared__ float smax[256];
    __shared__ int   sidx[256];
    __shared__ float ssum[256];

    float m = -1e30f; int mi = 0;
    for (int v = tid; v < V_; v += 256) {
        float x = lg[v];
        if (x > m) { m = x; mi = v; }
    }
    smax[tid] = m; sidx[tid] = mi;
    __syncthreads();
    for (int o = 128; o; o >>= 1) {
        if (tid < o) {
            float ov = smax[tid + o]; int oi = sidx[tid + o];
            if (ov > smax[tid] || (ov == smax[tid] && oi < sidx[tid])) {
                smax[tid] = ov; sidx[tid] = oi;
            }
        }
        __syncthreads();
    }
    float gm = smax[0];
    float s = 0.f;
    for (int v = tid; v < V_; v += 256) s += expf(lg[v] - gm);
    ssum[tid] = s;
    __syncthreads();
    for (int o = 128; o; o >>= 1) {
        if (tid < o) ssum[tid] += ssum[tid + o];
        __syncthreads();
    }
    float lse = logf(ssum[0]) + gm;
    float* out = lp_out + ((size_t)b * T_ + t) * V_;
    for (int v = tid; v < V_; v += 256) out[v] = lg[v] - lse;
    if (tid == 0) g_tok[b] = sidx[0];
}

// ---------------- final hidden out ----------------
__global__ void k_hidout(float* __restrict__ hid) {
    int idx = blockIdx.x * 256 + threadIdx.x;   // 32768
    int row = idx >> 5, b = idx & 31;
    int l = row >> 9, h = row & 511;
    hid[((size_t)l * 32 + b) * 512 + h] = g_query[0][row * 32 + b];
}

// ---------------- launcher ----------------
extern "C" void kernel_launch(void* const* d_in, const int* in_sizes, int n_in,
                              void* d_out, int out_size)
{
    const float* enc  = (const float*)d_in[0];
    const float* ehid = (const float*)d_in[1];
    const float* emb  = (const float*)d_in[3];
    const float* Wa   = (const float*)d_in[4];
    const float* ba   = (const float*)d_in[5];
    const float* Ua   = (const float*)d_in[6];
    const float* bua  = (const float*)d_in[7];
    const float* Va   = (const float*)d_in[8];
    const float* bva  = (const float*)d_in[9];
    const float* W0ih = (const float*)d_in[10];
    const float* W0hh = (const float*)d_in[11];
    const float* b0ih = (const float*)d_in[12];
    const float* b0hh = (const float*)d_in[13];
    const float* W1ih = (const float*)d_in[14];
    const float* W1hh = (const float*)d_in[15];
    const float* b1ih = (const float*)d_in[16];
    const float* b1hh = (const float*)d_in[17];
    const float* outW = (const float*)d_in[18];
    const float* outb = (const float*)d_in[19];

    float* out = (float*)d_out;
    const long long NLP  = (long long)B_ * T_ * V_;
    const long long NHID = 2LL * B_ * H_;
    const long long NATT = (long long)B_ * T_ * S_;
    bool full = (long long)out_size >= NLP + NHID + NATT;
    float* lp   = out;
    float* hid  = full ? out + NLP : nullptr;
    float* attn = full ? out + NLP + NHID : nullptr;

    k_init<<<128, 256>>>(ehid);
    k_ukeys<<<256, 256>>>(enc, Ua, bua);

    for (int t = 0; t < T_; t++) {
        int p = t & 1;
        k_pre3<<<64, 128>>>(Wa, W0hh, W1hh, p);
        k_attn<<<32, 256>>>(enc, emb, Va, bva, ba, attn, t);
        k_gi<<<48, 128>>>(W0ih, 1024, 4, 0, 0, 0);
        k_comb<<<64, 256>>>(0, p, b0ih, b0hh);
        k_gi<<<24, 128>>>(W1ih, 512, 2, 1, p ^ 1, 1);
        k_comb<<<64, 256>>>(1, p, b1ih, b1hh);
        k_logits<<<250, 128>>>(outW, outb, p ^ 1);
        k_softmax<<<32, 256>>>(lp, t);
    }
    if (hid)  k_hidout<<<128, 256>>>(hid);
}